// round 4
// baseline (speedup 1.0000x reference)
#include <cuda_runtime.h>

#define THREADS 128
#define H 64

// Stable softplus + sigmoid (matches jax.nn.softplus = logaddexp(x,0))
__device__ __forceinline__ void softsig(float x, float& sp, float& sg) {
    float e   = __expf(-fabsf(x));
    float inv = __fdividef(1.0f, 1.0f + e);
    sg = (x >= 0.0f) ? inv : e * inv;
    sp = fmaxf(x, 0.0f) + __logf(1.0f + e);
}

struct SW {
    float4 w1[H];      // (W1[k][0], W1[k][1], W1[k][2], b1[k])
    float2 c2[H];      // (W2[j][0], b2[j])
    float2 l3[H];      // (W3[0][j+1], W3[1][j+1])
    float  W2T[H * H]; // [k][j] = W2[j][k+1]   (transposed: inner j contiguous)
    float  MT [H * H]; // [k][j] = M[j][k]      (collapsed divergence matrix)
    float  t3_0, t3_1, b3_0, b3_1;
};

__global__ __launch_bounds__(THREADS)
void ffjord_kernel(const float* __restrict__ gz,  const float* __restrict__ glp,
                   const float* __restrict__ W1,  const float* __restrict__ b1,
                   const float* __restrict__ W2,  const float* __restrict__ b2,
                   const float* __restrict__ W3,  const float* __restrict__ b3,
                   float* __restrict__ out, int B)
{
    __shared__ SW s;
    const int tid = threadIdx.x;

    // Cooperative weight staging + M precompute (tiny: 4096 elems, L2-resident)
    for (int idx = tid; idx < H * H; idx += THREADS) {
        int j = idx & (H - 1);
        int k = idx >> 6;          // idx = k*64 + j
        float w2 = W2[j * 65 + k + 1];
        s.W2T[idx] = w2;
        s.MT[idx]  = w2 * (W3[j + 1] * W1[k * 3 + 1] + W3[65 + j + 1] * W1[k * 3 + 2]);
    }
    for (int k = tid; k < H; k += THREADS) {
        s.w1[k] = make_float4(W1[k * 3], W1[k * 3 + 1], W1[k * 3 + 2], b1[k]);
        s.c2[k] = make_float2(W2[k * 65], b2[k]);
        s.l3[k] = make_float2(W3[k + 1], W3[65 + k + 1]);
    }
    if (tid == 0) { s.t3_0 = W3[0]; s.t3_1 = W3[65]; s.b3_0 = b3[0]; s.b3_1 = b3[1]; }
    __syncthreads();

    const int i = blockIdx.x * THREADS + tid;
    if (i >= B) return;

    float z0 = gz[2 * i], z1 = gz[2 * i + 1];
    float lp = glp[i];
    const float dt = 0.25f;

    #pragma unroll 1
    for (int step = 0; step < 4; ++step) {
        const float t0 = (float)step * dt;
        float kz0 = 0.f, kz1 = 0.f, kl = 0.f;
        float az0 = 0.f, az1 = 0.f, al = 0.f;

        #pragma unroll 1
        for (int st = 0; st < 4; ++st) {
            // RK4 stage coefficients: c = {0, .5, .5, 1}, w = {1, 2, 2, 1}
            const float cs = (st == 0) ? 0.f : ((st == 3) ? 1.f : 0.5f);
            const float as = cs * dt;                 // input offset = c*dt * k_prev
            const float ws = (st == 0 || st == 3) ? 1.f : 2.f;
            const float t  = t0 + as;
            const float x0 = fmaf(as, kz0, z0);
            const float x1 = fmaf(as, kz1, z1);

            // ---- dynamics eval: z_dot = MLP(t,x), div = sg2' * M * sg1 ----
            float acc2[H], accM[H];
            #pragma unroll
            for (int j = 0; j < H; ++j) {
                float2 c = s.c2[j];
                acc2[j] = fmaf(c.x, t, c.y);
                accM[j] = 0.f;
            }

            #pragma unroll 1
            for (int k = 0; k < H; ++k) {
                float4 w   = s.w1[k];
                float  pre = fmaf(w.x, t, fmaf(w.y, x0, fmaf(w.z, x1, w.w)));
                float sp, sg;
                softsig(pre, sp, sg);
                const float4* wr = (const float4*)(s.W2T + k * H);
                const float4* mr = (const float4*)(s.MT  + k * H);
                #pragma unroll
                for (int q = 0; q < H / 4; ++q) {
                    float4 a = wr[q];
                    float4 m = mr[q];
                    acc2[4 * q + 0] = fmaf(a.x, sp, acc2[4 * q + 0]);
                    acc2[4 * q + 1] = fmaf(a.y, sp, acc2[4 * q + 1]);
                    acc2[4 * q + 2] = fmaf(a.z, sp, acc2[4 * q + 2]);
                    acc2[4 * q + 3] = fmaf(a.w, sp, acc2[4 * q + 3]);
                    accM[4 * q + 0] = fmaf(m.x, sg, accM[4 * q + 0]);
                    accM[4 * q + 1] = fmaf(m.y, sg, accM[4 * q + 1]);
                    accM[4 * q + 2] = fmaf(m.z, sg, accM[4 * q + 2]);
                    accM[4 * q + 3] = fmaf(m.w, sg, accM[4 * q + 3]);
                }
            }

            float zd0 = fmaf(s.t3_0, t, s.b3_0);
            float zd1 = fmaf(s.t3_1, t, s.b3_1);
            float dv  = 0.f;
            #pragma unroll
            for (int j = 0; j < H; ++j) {
                float sp, sg;
                softsig(acc2[j], sp, sg);
                float2 l = s.l3[j];
                zd0 = fmaf(l.x, sp, zd0);
                zd1 = fmaf(l.y, sp, zd1);
                dv  = fmaf(sg, accM[j], dv);
            }
            // ---------------------------------------------------------------

            kz0 = zd0; kz1 = zd1; kl = -dv;
            az0 = fmaf(ws, kz0, az0);
            az1 = fmaf(ws, kz1, az1);
            al  = fmaf(ws, kl,  al);
        }

        const float w6 = dt * (1.0f / 6.0f);
        z0 = fmaf(w6, az0, z0);
        z1 = fmaf(w6, az1, z1);
        lp = fmaf(w6, al,  lp);
    }

    out[2 * i]     = z0;
    out[2 * i + 1] = z1;
    out[2 * B + i] = lp;
}

extern "C" void kernel_launch(void* const* d_in, const int* in_sizes, int n_in,
                              void* d_out, int out_size) {
    const float* z   = (const float*)d_in[0];
    const float* lp  = (const float*)d_in[1];
    const float* W1  = (const float*)d_in[2];
    const float* b1  = (const float*)d_in[3];
    const float* W2  = (const float*)d_in[4];
    const float* b2  = (const float*)d_in[5];
    const float* W3  = (const float*)d_in[6];
    const float* b3  = (const float*)d_in[7];
    const int B = in_sizes[0] / 2;

    ffjord_kernel<<<(B + THREADS - 1) / THREADS, THREADS>>>(
        z, lp, W1, b1, W2, b2, W3, b3, (float*)d_out, B);
}

// round 5
// speedup vs baseline: 1.5723x; 1.5723x over previous
#include <cuda_runtime.h>

#define THREADS 128
#define H 64

// ---- packed fp32x2 helpers (FFMA2: 2 MACs per instruction, PTX-only) ----
__device__ __forceinline__ unsigned long long pack2(float lo, float hi) {
    unsigned long long r;
    asm("mov.b64 %0, {%1, %2};" : "=l"(r) : "f"(lo), "f"(hi));
    return r;
}
__device__ __forceinline__ unsigned long long fma2(unsigned long long a,
                                                   unsigned long long b,
                                                   unsigned long long c) {
    unsigned long long d;
    asm("fma.rn.f32x2 %0, %1, %2, %3;" : "=l"(d) : "l"(a), "l"(b), "l"(c));
    return d;
}
__device__ __forceinline__ float2 unpack2(unsigned long long v) {
    float lo, hi;
    asm("mov.b64 {%0, %1}, %2;" : "=f"(lo), "=f"(hi) : "l"(v));
    return make_float2(lo, hi);
}

// Stable softplus + sigmoid (matches jax.nn.softplus = logaddexp(x,0))
__device__ __forceinline__ void softsig(float x, float& sp, float& sg) {
    float e   = __expf(-fabsf(x));
    float inv = __fdividef(1.0f, 1.0f + e);
    sg = (x >= 0.0f) ? inv : e * inv;
    sp = fmaxf(x, 0.0f) + __logf(1.0f + e);
}

struct SW {
    float4 w1[H];          // (W1[k][0], W1[k][1], W1[k][2], b1[k])
    float2 c2[H];          // (W2[j][0], b2[j])
    float2 l3[H];          // (W3[0][j+1], W3[1][j+1])
    // W2T / MT stored interleaved at 16B granularity so the two half-threads
    // of a pair read bank-disjoint 16B chunks:
    //   element (k, j) lives at float4 index k*16 + 2*((j&31)>>2) + (j>>5), lane (j&3)
    float4 w2i[H * 16];    // W2T[k][j] = W2[j][k+1]
    float4 mti[H * 16];    // MT [k][j] = M[j][k]  (collapsed divergence matrix)
    float  t3_0, t3_1, b3_0, b3_1;
};

__global__ __launch_bounds__(THREADS, 4)
void ffjord_kernel(const float* __restrict__ gz,  const float* __restrict__ glp,
                   const float* __restrict__ W1,  const float* __restrict__ b1,
                   const float* __restrict__ W2,  const float* __restrict__ b2,
                   const float* __restrict__ W3,  const float* __restrict__ b3,
                   float* __restrict__ out, int B)
{
    __shared__ SW s;
    const int tid = threadIdx.x;

    // Cooperative weight staging + M precompute (weights-only, t-independent)
    {
        float* w2f = (float*)s.w2i;
        float* mtf = (float*)s.mti;
        for (int idx = tid; idx < H * H; idx += THREADS) {
            int k = idx >> 6, j = idx & 63;
            float w2 = W2[j * 65 + k + 1];
            float m  = w2 * (W3[j + 1] * W1[k * 3 + 1] + W3[65 + j + 1] * W1[k * 3 + 2]);
            int pos = (k * 16 + 2 * ((j & 31) >> 2) + (j >> 5)) * 4 + (j & 3);
            w2f[pos] = w2;
            mtf[pos] = m;
        }
        for (int k = tid; k < H; k += THREADS) {
            s.w1[k] = make_float4(W1[k * 3], W1[k * 3 + 1], W1[k * 3 + 2], b1[k]);
            s.c2[k] = make_float2(W2[k * 65], b2[k]);
            s.l3[k] = make_float2(W3[k + 1], W3[65 + k + 1]);
        }
        if (tid == 0) { s.t3_0 = W3[0]; s.t3_1 = W3[65]; s.b3_0 = b3[0]; s.b3_1 = b3[1]; }
    }
    __syncthreads();

    // Two threads per sample: hh selects which 32 of the 64 hidden units we own.
    const int gt = blockIdx.x * THREADS + tid;
    const int i  = gt >> 1;
    const int hh = gt & 1;
    if (i >= B) return;

    float z0 = gz[2 * i], z1 = gz[2 * i + 1];
    float lp = glp[i];
    const float dt = 0.25f;

    #pragma unroll 1
    for (int step = 0; step < 4; ++step) {
        const float t0 = (float)step * dt;
        float kz0 = 0.f, kz1 = 0.f, kl = 0.f;
        float az0 = 0.f, az1 = 0.f, al = 0.f;

        #pragma unroll 1
        for (int st = 0; st < 4; ++st) {
            // RK4: c = {0,.5,.5,1}, w = {1,2,2,1}
            const float cs = (st == 0) ? 0.f : ((st == 3) ? 1.f : 0.5f);
            const float as = cs * dt;
            const float ws = (st == 0 || st == 3) ? 1.f : 2.f;
            const float t  = t0 + as;
            const float x0 = fmaf(as, kz0, z0);
            const float x1 = fmaf(as, kz1, z1);

            // ---- dynamics eval: z_dot = MLP(t,x), div = sg2' * M * sg1 ----
            unsigned long long acc2[16], accM[16];
            #pragma unroll
            for (int q = 0; q < 8; ++q) {
                int j = hh * 32 + 4 * q;
                float2 c0 = s.c2[j],     c1 = s.c2[j + 1];
                float2 c2v = s.c2[j + 2], c3 = s.c2[j + 3];
                acc2[2 * q]     = pack2(fmaf(c0.x, t, c0.y),  fmaf(c1.x, t, c1.y));
                acc2[2 * q + 1] = pack2(fmaf(c2v.x, t, c2v.y), fmaf(c3.x, t, c3.y));
                accM[2 * q]     = 0ull;
                accM[2 * q + 1] = 0ull;
            }

            #pragma unroll 1
            for (int k = 0; k < H; ++k) {
                float4 w   = s.w1[k];
                float  pre = fmaf(w.x, t, fmaf(w.y, x0, fmaf(w.z, x1, w.w)));
                float sp, sg;
                softsig(pre, sp, sg);
                unsigned long long spsp = pack2(sp, sp);
                unsigned long long sgsg = pack2(sg, sg);
                const ulonglong2* wp = (const ulonglong2*)(s.w2i + k * 16 + hh);
                const ulonglong2* mp = (const ulonglong2*)(s.mti + k * 16 + hh);
                #pragma unroll
                for (int q = 0; q < 8; ++q) {
                    ulonglong2 a = wp[2 * q];
                    ulonglong2 m = mp[2 * q];
                    acc2[2 * q]     = fma2(a.x, spsp, acc2[2 * q]);
                    acc2[2 * q + 1] = fma2(a.y, spsp, acc2[2 * q + 1]);
                    accM[2 * q]     = fma2(m.x, sgsg, accM[2 * q]);
                    accM[2 * q + 1] = fma2(m.y, sgsg, accM[2 * q + 1]);
                }
            }

            // Partial layer-3 + divergence over our 32 hidden units
            float zd0p = 0.f, zd1p = 0.f, dvp = 0.f;
            #pragma unroll
            for (int q = 0; q < 8; ++q) {
                float2 a0 = unpack2(acc2[2 * q]),  a1 = unpack2(acc2[2 * q + 1]);
                float2 m0 = unpack2(accM[2 * q]),  m1 = unpack2(accM[2 * q + 1]);
                int j = hh * 32 + 4 * q;
                float sp, sg; float2 l;
                softsig(a0.x, sp, sg); l = s.l3[j];
                zd0p = fmaf(l.x, sp, zd0p); zd1p = fmaf(l.y, sp, zd1p); dvp = fmaf(sg, m0.x, dvp);
                softsig(a0.y, sp, sg); l = s.l3[j + 1];
                zd0p = fmaf(l.x, sp, zd0p); zd1p = fmaf(l.y, sp, zd1p); dvp = fmaf(sg, m0.y, dvp);
                softsig(a1.x, sp, sg); l = s.l3[j + 2];
                zd0p = fmaf(l.x, sp, zd0p); zd1p = fmaf(l.y, sp, zd1p); dvp = fmaf(sg, m1.x, dvp);
                softsig(a1.y, sp, sg); l = s.l3[j + 3];
                zd0p = fmaf(l.x, sp, zd0p); zd1p = fmaf(l.y, sp, zd1p); dvp = fmaf(sg, m1.y, dvp);
            }

            // Merge the pair's halves (lanes 2m <-> 2m+1)
            zd0p += __shfl_xor_sync(0xffffffffu, zd0p, 1);
            zd1p += __shfl_xor_sync(0xffffffffu, zd1p, 1);
            dvp  += __shfl_xor_sync(0xffffffffu, dvp,  1);

            const float zd0 = fmaf(s.t3_0, t, s.b3_0) + zd0p;
            const float zd1 = fmaf(s.t3_1, t, s.b3_1) + zd1p;
            // ---------------------------------------------------------------

            kz0 = zd0; kz1 = zd1; kl = -dvp;
            az0 = fmaf(ws, kz0, az0);
            az1 = fmaf(ws, kz1, az1);
            al  = fmaf(ws, kl,  al);
        }

        const float w6 = dt * (1.0f / 6.0f);
        z0 = fmaf(w6, az0, z0);
        z1 = fmaf(w6, az1, z1);
        lp = fmaf(w6, al,  lp);
    }

    if (hh == 0) {
        out[2 * i]     = z0;
        out[2 * i + 1] = z1;
        out[2 * B + i] = lp;
    }
}

extern "C" void kernel_launch(void* const* d_in, const int* in_sizes, int n_in,
                              void* d_out, int out_size) {
    const float* z   = (const float*)d_in[0];
    const float* lp  = (const float*)d_in[1];
    const float* W1  = (const float*)d_in[2];
    const float* b1  = (const float*)d_in[3];
    const float* W2  = (const float*)d_in[4];
    const float* b2  = (const float*)d_in[5];
    const float* W3  = (const float*)d_in[6];
    const float* b3  = (const float*)d_in[7];
    const int B = in_sizes[0] / 2;

    const int total = 2 * B;
    ffjord_kernel<<<(total + THREADS - 1) / THREADS, THREADS>>>(
        z, lp, W1, b1, W2, b2, W3, b3, (float*)d_out, B);
}

// round 9
// speedup vs baseline: 1.6931x; 1.0768x over previous
#include <cuda_runtime.h>

#define THREADS 128
#define H 64
#define JS 16   // j-slice per thread (4 threads per sample-pair)

// ---- packed fp32x2 helpers (FFMA2: 2 MACs per instruction, PTX-only) ----
__device__ __forceinline__ unsigned long long pack2(float lo, float hi) {
    unsigned long long r;
    asm("mov.b64 %0, {%1, %2};" : "=l"(r) : "f"(lo), "f"(hi));
    return r;
}
__device__ __forceinline__ unsigned long long fma2(unsigned long long a,
                                                   unsigned long long b,
                                                   unsigned long long c) {
    unsigned long long d;
    asm("fma.rn.f32x2 %0, %1, %2, %3;" : "=l"(d) : "l"(a), "l"(b), "l"(c));
    return d;
}
__device__ __forceinline__ float2 unpack2(unsigned long long v) {
    float lo, hi;
    asm("mov.b64 {%0, %1}, %2;" : "=f"(lo), "=f"(hi) : "l"(v));
    return make_float2(lo, hi);
}

// Stable softplus + sigmoid, 3 MUFU (ex2, rcp, lg2), reusing inv for the log:
// softplus(x) = max(x,0) + log(1+e^{-|x|}) = max(x,0) - ln2*log2(inv)
__device__ __forceinline__ void softsig(float x, float& sp, float& sg) {
    float e   = __expf(-fabsf(x));
    float inv = __fdividef(1.0f, 1.0f + e);
    sg = (x >= 0.0f) ? inv : e * inv;
    sp = fmaf(__log2f(inv), -0.69314718056f, fmaxf(x, 0.0f));
}

struct SW {
    float4 w1[H];          // (W1[k][0], W1[k][1], W1[k][2], b1[k])
    float2 c2[H];          // (W2[j][0], b2[j])
    float2 l3[H];          // (W3[0][j+1], W3[1][j+1])
    // Row k is 16 float4 chunks; chunk p = i*4 + sub holds j = sub*16 + i*4 .. +3.
    // The 4 subs' loads at step i are 16B-contiguous (64B span) -> bank-disjoint.
    float4 w2i[H * 16];    // W2T[k][j] = W2[j][k+1]
    float4 mti[H * 16];    // MT [k][j] = M[j][k]  (collapsed divergence matrix)
    float  t3_0, t3_1, b3_0, b3_1;
};

__global__ __launch_bounds__(THREADS, 3)
void ffjord_kernel(const float* __restrict__ gz,  const float* __restrict__ glp,
                   const float* __restrict__ W1,  const float* __restrict__ b1,
                   const float* __restrict__ W2,  const float* __restrict__ b2,
                   const float* __restrict__ W3,  const float* __restrict__ b3,
                   float* __restrict__ out, int B)
{
    __shared__ SW s;
    const int tid = threadIdx.x;

    // Cooperative weight staging + M precompute (weights-only, t-independent)
    {
        float* w2f = (float*)s.w2i;
        float* mtf = (float*)s.mti;
        for (int idx = tid; idx < H * H; idx += THREADS) {
            int k = idx >> 6, j = idx & 63;
            float w2 = W2[j * 65 + k + 1];
            float m  = w2 * (W3[j + 1] * W1[k * 3 + 1] + W3[65 + j + 1] * W1[k * 3 + 2]);
            int p   = ((j >> 2) & 3) * 4 + (j >> 4);          // chunk permutation
            int pos = (k * 16 + p) * 4 + (j & 3);
            w2f[pos] = w2;
            mtf[pos] = m;
        }
        for (int k = tid; k < H; k += THREADS) {
            s.w1[k] = make_float4(W1[k * 3], W1[k * 3 + 1], W1[k * 3 + 2], b1[k]);
            s.c2[k] = make_float2(W2[k * 65], b2[k]);
            s.l3[k] = make_float2(W3[k + 1], W3[65 + k + 1]);
        }
        if (tid == 0) { s.t3_0 = W3[0]; s.t3_1 = W3[65]; s.b3_0 = b3[0]; s.b3_1 = b3[1]; }
    }
    __syncthreads();

    // 4-thread group g handles samples {2g, 2g+1}; sub owns j in [sub*16, sub*16+16)
    const int gt  = blockIdx.x * THREADS + tid;
    const int g   = gt >> 2;
    const int sub = gt & 3;
    if (2 * g >= B) return;

    const float4 zz = ((const float4*)gz)[g];       // (zA0, zA1, zB0, zB1)
    const float2 lv = ((const float2*)glp)[g];
    float zA0 = zz.x, zA1 = zz.y, zB0 = zz.z, zB1 = zz.w;
    float lpA = lv.x, lpB = lv.y;
    const float dt = 0.25f;

    #pragma unroll 1
    for (int step = 0; step < 4; ++step) {
        const float t0 = (float)step * dt;
        float kzA0 = 0.f, kzA1 = 0.f, klA = 0.f, azA0 = 0.f, azA1 = 0.f, alA = 0.f;
        float kzB0 = 0.f, kzB1 = 0.f, klB = 0.f, azB0 = 0.f, azB1 = 0.f, alB = 0.f;

        #pragma unroll 1
        for (int st = 0; st < 4; ++st) {
            // RK4: c = {0,.5,.5,1}, w = {1,2,2,1}
            const float cs = (st == 0) ? 0.f : ((st == 3) ? 1.f : 0.5f);
            const float as = cs * dt;
            const float ws = (st == 0 || st == 3) ? 1.f : 2.f;
            const float t  = t0 + as;
            const float xA0 = fmaf(as, kzA0, zA0), xA1 = fmaf(as, kzA1, zA1);
            const float xB0 = fmaf(as, kzB0, zB0), xB1 = fmaf(as, kzB1, zB1);

            // ---- dynamics eval for both samples ----
            unsigned long long aA2[8], aAM[8], aB2[8], aBM[8];
            #pragma unroll
            for (int i = 0; i < 4; ++i) {
                int j = sub * JS + 4 * i;
                float2 c0 = s.c2[j],     c1 = s.c2[j + 1];
                float2 c2v = s.c2[j + 2], c3 = s.c2[j + 3];
                unsigned long long v0 = pack2(fmaf(c0.x, t, c0.y),  fmaf(c1.x, t, c1.y));
                unsigned long long v1 = pack2(fmaf(c2v.x, t, c2v.y), fmaf(c3.x, t, c3.y));
                aA2[2 * i] = v0;  aA2[2 * i + 1] = v1;
                aB2[2 * i] = v0;  aB2[2 * i + 1] = v1;
                aAM[2 * i] = 0ull; aAM[2 * i + 1] = 0ull;
                aBM[2 * i] = 0ull; aBM[2 * i + 1] = 0ull;
            }

            #pragma unroll 1
            for (int k = 0; k < H; ++k) {
                float4 w  = s.w1[k];
                float  tb = fmaf(w.x, t, w.w);
                float preA = fmaf(w.y, xA0, fmaf(w.z, xA1, tb));
                float preB = fmaf(w.y, xB0, fmaf(w.z, xB1, tb));
                float spA, sgA, spB, sgB;
                softsig(preA, spA, sgA);
                softsig(preB, spB, sgB);
                unsigned long long spA2 = pack2(spA, spA), sgA2 = pack2(sgA, sgA);
                unsigned long long spB2 = pack2(spB, spB), sgB2 = pack2(sgB, sgB);
                const ulonglong2* wr = (const ulonglong2*)(s.w2i + k * 16 + sub);
                const ulonglong2* mr = (const ulonglong2*)(s.mti + k * 16 + sub);
                #pragma unroll
                for (int i = 0; i < 4; ++i) {
                    ulonglong2 a = wr[4 * i];
                    ulonglong2 m = mr[4 * i];
                    aA2[2 * i]     = fma2(a.x, spA2, aA2[2 * i]);
                    aA2[2 * i + 1] = fma2(a.y, spA2, aA2[2 * i + 1]);
                    aB2[2 * i]     = fma2(a.x, spB2, aB2[2 * i]);
                    aB2[2 * i + 1] = fma2(a.y, spB2, aB2[2 * i + 1]);
                    aAM[2 * i]     = fma2(m.x, sgA2, aAM[2 * i]);
                    aAM[2 * i + 1] = fma2(m.y, sgA2, aAM[2 * i + 1]);
                    aBM[2 * i]     = fma2(m.x, sgB2, aBM[2 * i]);
                    aBM[2 * i + 1] = fma2(m.y, sgB2, aBM[2 * i + 1]);
                }
            }

            // Partial layer-3 + divergence over our 16 hidden units, per sample
            float zd0A = 0.f, zd1A = 0.f, dvA = 0.f;
            float zd0B = 0.f, zd1B = 0.f, dvB = 0.f;
            #pragma unroll
            for (int n = 0; n < 8; ++n) {
                int j = sub * JS + 2 * n;
                float2 l0 = s.l3[j], l1 = s.l3[j + 1];
                float2 vA = unpack2(aA2[n]), mA = unpack2(aAM[n]);
                float2 vB = unpack2(aB2[n]), mB = unpack2(aBM[n]);
                float sp, sg;
                softsig(vA.x, sp, sg);
                zd0A = fmaf(l0.x, sp, zd0A); zd1A = fmaf(l0.y, sp, zd1A); dvA = fmaf(sg, mA.x, dvA);
                softsig(vA.y, sp, sg);
                zd0A = fmaf(l1.x, sp, zd0A); zd1A = fmaf(l1.y, sp, zd1A); dvA = fmaf(sg, mA.y, dvA);
                softsig(vB.x, sp, sg);
                zd0B = fmaf(l0.x, sp, zd0B); zd1B = fmaf(l0.y, sp, zd1B); dvB = fmaf(sg, mB.x, dvB);
                softsig(vB.y, sp, sg);
                zd0B = fmaf(l1.x, sp, zd0B); zd1B = fmaf(l1.y, sp, zd1B); dvB = fmaf(sg, mB.y, dvB);
            }

            // Reduce across the 4 subs (lanes of the group)
            #pragma unroll
            for (int d = 1; d < 4; d <<= 1) {
                zd0A += __shfl_xor_sync(0xffffffffu, zd0A, d);
                zd1A += __shfl_xor_sync(0xffffffffu, zd1A, d);
                dvA  += __shfl_xor_sync(0xffffffffu, dvA,  d);
                zd0B += __shfl_xor_sync(0xffffffffu, zd0B, d);
                zd1B += __shfl_xor_sync(0xffffffffu, zd1B, d);
                dvB  += __shfl_xor_sync(0xffffffffu, dvB,  d);
            }

            kzA0 = fmaf(s.t3_0, t, s.b3_0) + zd0A;
            kzA1 = fmaf(s.t3_1, t, s.b3_1) + zd1A;
            klA  = -dvA;
            kzB0 = fmaf(s.t3_0, t, s.b3_0) + zd0B;
            kzB1 = fmaf(s.t3_1, t, s.b3_1) + zd1B;
            klB  = -dvB;
            // ----------------------------------------

            azA0 = fmaf(ws, kzA0, azA0); azA1 = fmaf(ws, kzA1, azA1); alA = fmaf(ws, klA, alA);
            azB0 = fmaf(ws, kzB0, azB0); azB1 = fmaf(ws, kzB1, azB1); alB = fmaf(ws, klB, alB);
        }

        const float w6 = dt * (1.0f / 6.0f);
        zA0 = fmaf(w6, azA0, zA0); zA1 = fmaf(w6, azA1, zA1); lpA = fmaf(w6, alA, lpA);
        zB0 = fmaf(w6, azB0, zB0); zB1 = fmaf(w6, azB1, zB1); lpB = fmaf(w6, alB, lpB);
    }

    if (sub == 0) {
        ((float4*)out)[g] = make_float4(zA0, zA1, zB0, zB1);
        ((float2*)(out + 2 * B))[g] = make_float2(lpA, lpB);
    }
}

extern "C" void kernel_launch(void* const* d_in, const int* in_sizes, int n_in,
                              void* d_out, int out_size) {
    const float* z   = (const float*)d_in[0];
    const float* lp  = (const float*)d_in[1];
    const float* W1  = (const float*)d_in[2];
    const float* b1  = (const float*)d_in[3];
    const float* W2  = (const float*)d_in[4];
    const float* b2  = (const float*)d_in[5];
    const float* W3  = (const float*)d_in[6];
    const float* b3  = (const float*)d_in[7];
    const int B = in_sizes[0] / 2;

    const int total = 2 * B;   // 4 threads per 2 samples
    ffjord_kernel<<<(total + THREADS - 1) / THREADS, THREADS>>>(
        z, lp, W1, b1, W2, b2, W3, b3, (float*)d_out, B);
}

// round 14
// speedup vs baseline: 1.9389x; 1.1452x over previous
#include <cuda_runtime.h>

#define THREADS 128
#define H 64

// ---- packed fp32x2 helpers (FFMA2: 2 MACs per instruction, PTX-only) ----
__device__ __forceinline__ unsigned long long pack2(float lo, float hi) {
    unsigned long long r;
    asm("mov.b64 %0, {%1, %2};" : "=l"(r) : "f"(lo), "f"(hi));
    return r;
}
__device__ __forceinline__ unsigned long long fma2(unsigned long long a,
                                                   unsigned long long b,
                                                   unsigned long long c) {
    unsigned long long d;
    asm("fma.rn.f32x2 %0, %1, %2, %3;" : "=l"(d) : "l"(a), "l"(b), "l"(c));
    return d;
}
__device__ __forceinline__ float2 unpack2(unsigned long long v) {
    float lo, hi;
    asm("mov.b64 {%0, %1}, %2;" : "=f"(lo), "=f"(hi) : "l"(v));
    return make_float2(lo, hi);
}

// Stable softplus + sigmoid (3 MUFU: ex2, rcp, lg2)
__device__ __forceinline__ void softsig(float x, float& sp, float& sg) {
    float e   = __expf(-fabsf(x));
    float inv = __fdividef(1.0f, 1.0f + e);
    sg = (x >= 0.0f) ? inv : e * inv;
    sp = fmaf(__log2f(inv), -0.69314718056f, fmaxf(x, 0.0f));
}

struct SWd {
    float4 w1[H];        // (W1[k][0], W1[k][1], W1[k][2], b1[k])
    float2 c2[H];        // (W2[j][0], b2[j])
    float2 l3[H];        // (W3[0][j+1], W3[1][j+1])
    float2 xs[H];        // per-CTA-local-sample stage input (x0, x1)
    float  t3b[4];       // t3_0, t3_1, b3_0, b3_1
    float  w2r[H * H];   // [k][j] = W2[j][k+1]
    float  mtr[H * H];   // [k][j] = M[j][k]   (collapsed divergence matrix)
    float  sps[H * H];   // [k][s] softplus(pre1)
    float  sgs[H * H];   // [k][s] sigmoid(pre1)
};

__global__ __launch_bounds__(THREADS, 3)
void ffjord_kernel(const float* __restrict__ gz,  const float* __restrict__ glp,
                   const float* __restrict__ W1,  const float* __restrict__ b1,
                   const float* __restrict__ W2,  const float* __restrict__ b2,
                   const float* __restrict__ W3,  const float* __restrict__ b3,
                   float* __restrict__ out, int B)
{
    extern __shared__ char smraw[];
    SWd& s = *reinterpret_cast<SWd*>(smraw);
    const int tid = threadIdx.x;

    // ---- cooperative weight staging + M precompute ----
    for (int idx = tid; idx < H * H; idx += THREADS) {
        int k = idx >> 6, j = idx & 63;
        float w2 = W2[j * 65 + k + 1];
        s.w2r[k * H + j] = w2;
        s.mtr[k * H + j] = w2 * (W3[j + 1] * W1[k * 3 + 1] + W3[65 + j + 1] * W1[k * 3 + 2]);
    }
    for (int k = tid; k < H; k += THREADS) {
        s.w1[k] = make_float4(W1[k * 3], W1[k * 3 + 1], W1[k * 3 + 2], b1[k]);
        s.c2[k] = make_float2(W2[k * 65], b2[k]);
        s.l3[k] = make_float2(W3[k + 1], W3[65 + k + 1]);
    }
    if (tid == 0) { s.t3b[0] = W3[0]; s.t3b[1] = W3[65]; s.t3b[2] = b3[0]; s.t3b[3] = b3[1]; }

    // ---- lane decomposition: 2 arrays x 8 j-groups x 2 sample-groups ----
    const int warp = tid >> 5, lane = tid & 31;
    const int arr  = lane >> 4;          // 0 = W2/acc2, 1 = M/accM
    const int sgrp = (lane >> 3) & 1;    // which 8 of the warp's 16 samples
    const int j0   = (lane & 7) * 8;     // lane's 8-j slice
    const int wb   = warp * 16;          // warp sample base (CTA-local)
    const int sb   = wb + sgrp * 8;      // lane's 8-sample base

    // staging decomposition: thread owns 8 k's x 4 samples
    const int kk = tid & 7;              // k = kk*8 + i
    const int sc = tid >> 3;             // samples 4sc .. 4sc+3

    const bool owner = (lane < 16);      // lane l owns CTA-local sample wb + l
    const int  gs    = blockIdx.x * 64 + wb + lane;   // owner's global sample

    float z0 = 0.f, z1 = 0.f, lp = 0.f;
    if (owner && gs < B) {
        float2 zv = ((const float2*)gz)[gs];
        z0 = zv.x; z1 = zv.y; lp = glp[gs];
    }

    const float dt = 0.25f;
    float kz0 = 0.f, kz1 = 0.f;

    #pragma unroll 1
    for (int step = 0; step < 4; ++step) {
        const float t0 = (float)step * dt;
        float az0 = 0.f, az1 = 0.f, al = 0.f;
        kz0 = 0.f; kz1 = 0.f;

        #pragma unroll 1
        for (int st = 0; st < 4; ++st) {
            const float cs = (st == 0) ? 0.f : ((st == 3) ? 1.f : 0.5f);
            const float as = cs * dt;
            const float ws = (st == 0 || st == 3) ? 1.f : 2.f;
            const float t  = t0 + as;

            // owner publishes this stage's input
            if (owner) {
                s.xs[wb + lane] = make_float2(fmaf(as, kz0, z0), fmaf(as, kz1, z1));
            }
            __syncthreads();   // also fences prior eval's sps/sgs reads

            // ---- layer-1 staging: softsig computed ONCE per (sample,k) ----
            {
                float2 x0v = s.xs[4 * sc + 0], x1v = s.xs[4 * sc + 1];
                float2 x2v = s.xs[4 * sc + 2], x3v = s.xs[4 * sc + 3];
                #pragma unroll
                for (int i = 0; i < 8; ++i) {
                    int k = kk * 8 + i;
                    float4 w  = s.w1[k];
                    float  tb = fmaf(w.x, t, w.w);
                    float p0 = fmaf(w.y, x0v.x, fmaf(w.z, x0v.y, tb));
                    float p1 = fmaf(w.y, x1v.x, fmaf(w.z, x1v.y, tb));
                    float p2 = fmaf(w.y, x2v.x, fmaf(w.z, x2v.y, tb));
                    float p3 = fmaf(w.y, x3v.x, fmaf(w.z, x3v.y, tb));
                    float sp0, sg0, sp1, sg1, sp2, sg2, sp3, sg3;
                    softsig(p0, sp0, sg0); softsig(p1, sp1, sg1);
                    softsig(p2, sp2, sg2); softsig(p3, sp3, sg3);
                    *(float4*)(s.sps + k * H + 4 * sc) = make_float4(sp0, sp1, sp2, sp3);
                    *(float4*)(s.sgs + k * H + 4 * sc) = make_float4(sg0, sg1, sg2, sg3);
                }
            }
            __syncthreads();

            // ---- k-loop: lane accumulates its (array, 8j, 8s) tile ----
            unsigned long long acc[4][8];
            if (arr == 0) {
                #pragma unroll
                for (int p = 0; p < 4; ++p) {
                    float4 cq = ((const float4*)s.c2)[(j0 >> 1) + p];
                    unsigned long long ip = pack2(fmaf(cq.x, t, cq.y), fmaf(cq.z, t, cq.w));
                    #pragma unroll
                    for (int q = 0; q < 8; ++q) acc[p][q] = ip;
                }
            } else {
                #pragma unroll
                for (int p = 0; p < 4; ++p)
                    #pragma unroll
                    for (int q = 0; q < 8; ++q) acc[p][q] = 0ull;
            }

            const float* wp = (arr ? s.mtr : s.w2r) + j0;
            const float* ap = (arr ? s.sgs : s.sps) + sb;

            #pragma unroll 2
            for (int k = 0; k < H; ++k) {
                const ulonglong2* wr = (const ulonglong2*)(wp + k * H);
                ulonglong2 pA = wr[0], pB = wr[1];
                float4 a0 = *(const float4*)(ap + k * H);
                float4 a1 = *(const float4*)(ap + k * H + 4);
                unsigned long long ds[8];
                ds[0] = pack2(a0.x, a0.x); ds[1] = pack2(a0.y, a0.y);
                ds[2] = pack2(a0.z, a0.z); ds[3] = pack2(a0.w, a0.w);
                ds[4] = pack2(a1.x, a1.x); ds[5] = pack2(a1.y, a1.y);
                ds[6] = pack2(a1.z, a1.z); ds[7] = pack2(a1.w, a1.w);
                #pragma unroll
                for (int q = 0; q < 8; ++q) {
                    acc[0][q] = fma2(pA.x, ds[q], acc[0][q]);
                    acc[1][q] = fma2(pA.y, ds[q], acc[1][q]);
                    acc[2][q] = fma2(pB.x, ds[q], acc[2][q]);
                    acc[3][q] = fma2(pB.y, ds[q], acc[3][q]);
                }
            }

            // ---- epilogue: softsig(acc2), cross-array shfl for div, reduce ----
            float zd0p[8], zd1p[8], dvp[8];
            #pragma unroll
            for (int q = 0; q < 8; ++q) { zd0p[q] = 0.f; zd1p[q] = 0.f; dvp[q] = 0.f; }

            #pragma unroll
            for (int p = 0; p < 4; ++p) {
                float4 lq = ((const float4*)s.l3)[(j0 >> 1) + p];
                #pragma unroll
                for (int q = 0; q < 8; ++q) {
                    float2 av = unpack2(acc[p][q]);
                    float m0 = __shfl_sync(0xffffffffu, av.x, lane | 16, 32);
                    float m1 = __shfl_sync(0xffffffffu, av.y, lane | 16, 32);
                    float sp0, sg0, sp1, sg1;
                    softsig(av.x, sp0, sg0);
                    softsig(av.y, sp1, sg1);
                    zd0p[q] = fmaf(lq.x, sp0, fmaf(lq.z, sp1, zd0p[q]));
                    zd1p[q] = fmaf(lq.y, sp0, fmaf(lq.w, sp1, zd1p[q]));
                    dvp[q]  = fmaf(sg0, m0, fmaf(sg1, m1, dvp[q]));
                }
            }

            // butterfly over the 8 j-groups (stays within each 8-lane octet)
            #pragma unroll
            for (int d = 1; d < 8; d <<= 1) {
                #pragma unroll
                for (int q = 0; q < 8; ++q) {
                    zd0p[q] += __shfl_xor_sync(0xffffffffu, zd0p[q], d, 32);
                    zd1p[q] += __shfl_xor_sync(0xffffffffu, zd1p[q], d, 32);
                    dvp[q]  += __shfl_xor_sync(0xffffffffu, dvp[q],  d, 32);
                }
            }

            // owner (lane < 16) selects its own sample's totals
            float rz0 = 0.f, rz1 = 0.f, rdv = 0.f;
            #pragma unroll
            for (int q = 0; q < 8; ++q)
                if ((lane & 7) == q) { rz0 = zd0p[q]; rz1 = zd1p[q]; rdv = dvp[q]; }

            kz0 = fmaf(s.t3b[0], t, s.t3b[2]) + rz0;
            kz1 = fmaf(s.t3b[1], t, s.t3b[3]) + rz1;
            const float klv = -rdv;

            az0 = fmaf(ws, kz0, az0);
            az1 = fmaf(ws, kz1, az1);
            al  = fmaf(ws, klv, al);
        }

        const float w6 = dt * (1.0f / 6.0f);
        z0 = fmaf(w6, az0, z0);
        z1 = fmaf(w6, az1, z1);
        lp = fmaf(w6, al,  lp);
    }

    if (owner && gs < B) {
        ((float2*)out)[gs] = make_float2(z0, z1);
        out[2 * B + gs] = lp;
    }
}

extern "C" void kernel_launch(void* const* d_in, const int* in_sizes, int n_in,
                              void* d_out, int out_size) {
    const float* z   = (const float*)d_in[0];
    const float* lp  = (const float*)d_in[1];
    const float* W1  = (const float*)d_in[2];
    const float* b1  = (const float*)d_in[3];
    const float* W2  = (const float*)d_in[4];
    const float* b2  = (const float*)d_in[5];
    const float* W3  = (const float*)d_in[6];
    const float* b3  = (const float*)d_in[7];
    const int B = in_sizes[0] / 2;

    const int smem = (int)sizeof(SWd);
    cudaFuncSetAttribute(ffjord_kernel, cudaFuncAttributeMaxDynamicSharedMemorySize, smem);

    const int blocks = (B + 63) / 64;   // 64 samples per CTA
    ffjord_kernel<<<blocks, THREADS, smem>>>(
        z, lp, W1, b1, W2, b2, W3, b3, (float*)d_out, B);
}

// round 16
// speedup vs baseline: 2.2631x; 1.1672x over previous
#include <cuda_runtime.h>

#define THREADS 128
#define H 64

// ---- packed fp32x2 helpers (FFMA2: 2 MACs per instruction, PTX-only) ----
__device__ __forceinline__ unsigned long long pack2(float lo, float hi) {
    unsigned long long r;
    asm("mov.b64 %0, {%1, %2};" : "=l"(r) : "f"(lo), "f"(hi));
    return r;
}
__device__ __forceinline__ unsigned long long fma2(unsigned long long a,
                                                   unsigned long long b,
                                                   unsigned long long c) {
    unsigned long long d;
    asm("fma.rn.f32x2 %0, %1, %2, %3;" : "=l"(d) : "l"(a), "l"(b), "l"(c));
    return d;
}
__device__ __forceinline__ float2 unpack2(unsigned long long v) {
    float lo, hi;
    asm("mov.b64 {%0, %1}, %2;" : "=f"(lo), "=f"(hi) : "l"(v));
    return make_float2(lo, hi);
}

// Stable softplus + sigmoid (3 MUFU: ex2, rcp, lg2)
__device__ __forceinline__ void softsig(float x, float& sp, float& sg) {
    float e   = __expf(-fabsf(x));
    float inv = __fdividef(1.0f, 1.0f + e);
    sg = (x >= 0.0f) ? inv : e * inv;
    sp = fmaf(__log2f(inv), -0.69314718056f, fmaxf(x, 0.0f));
}

struct SWd {
    float4 w1[H];        // XOR-permuted: logical k stored at k ^ (k>>3)
    float2 c2[H];        // (W2[j][0], b2[j])
    float2 l3[H];        // (W3[0][j+1], W3[1][j+1])
    float2 xs[H];        // per-CTA-local-sample stage input (x0, x1)
    float  t3b[4];       // t3_0, t3_1, b3_0, b3_1
    float  w2r[H * H];   // [k][j] = W2[j][k+1]
    float  mtr[H * H];   // [k][j] = M[j][k]   (collapsed divergence matrix)
    float  sps[H * H];   // [k][swz(col)] softplus(pre1); col swizzle +4*(k>>3) mod 64
    float  sgs[H * H];   // [k][swz(col)] sigmoid(pre1)
};

__global__ __launch_bounds__(THREADS, 3)
void ffjord_kernel(const float* __restrict__ gz,  const float* __restrict__ glp,
                   const float* __restrict__ W1,  const float* __restrict__ b1,
                   const float* __restrict__ W2,  const float* __restrict__ b2,
                   const float* __restrict__ W3,  const float* __restrict__ b3,
                   float* __restrict__ out, int B)
{
    extern __shared__ char smraw[];
    SWd& s = *reinterpret_cast<SWd*>(smraw);
    const int tid = threadIdx.x;

    // ---- cooperative weight staging + M precompute ----
    for (int idx = tid; idx < H * H; idx += THREADS) {
        int k = idx >> 6, j = idx & 63;
        float w2 = W2[j * 65 + k + 1];
        s.w2r[k * H + j] = w2;
        s.mtr[k * H + j] = w2 * (W3[j + 1] * W1[k * 3 + 1] + W3[65 + j + 1] * W1[k * 3 + 2]);
    }
    for (int k = tid; k < H; k += THREADS) {
        s.w1[k ^ (k >> 3)] = make_float4(W1[k * 3], W1[k * 3 + 1], W1[k * 3 + 2], b1[k]);
        s.c2[k] = make_float2(W2[k * 65], b2[k]);
        s.l3[k] = make_float2(W3[k + 1], W3[65 + k + 1]);
    }
    if (tid == 0) { s.t3b[0] = W3[0]; s.t3b[1] = W3[65]; s.t3b[2] = b3[0]; s.t3b[3] = b3[1]; }

    // ---- lane decomposition: 2 arrays x 8 j-groups x 2 sample-groups ----
    const int warp = tid >> 5, lane = tid & 31;
    const int arr  = lane >> 4;          // 0 = W2/acc2, 1 = M/accM
    const int sgrp = (lane >> 3) & 1;    // which 8 of the warp's 16 samples
    const int js   = lane & 7;           // lane's j-slice: {4js..4js+3, 32+4js..+3}
    const int wb   = warp * 16;          // warp sample base (CTA-local)
    const int sbl  = wb + sgrp * 8;      // lane's 8-sample base (CTA-local col)

    // staging decomposition: thread owns 8 k's x 4 samples
    const int kk = tid & 7;              // k = kk*8 + i
    const int sc = tid >> 3;             // samples 4sc .. 4sc+3

    const bool owner = (lane < 16);      // lane l owns CTA-local sample wb + l
    const int  gs    = blockIdx.x * 64 + wb + lane;   // owner's global sample

    float z0 = 0.f, z1 = 0.f, lp = 0.f;
    if (owner && gs < B) {
        float2 zv = ((const float2*)gz)[gs];
        z0 = zv.x; z1 = zv.y; lp = glp[gs];
    }

    const float dt = 0.25f;
    float kz0 = 0.f, kz1 = 0.f;

    #pragma unroll 1
    for (int step = 0; step < 4; ++step) {
        const float t0 = (float)step * dt;
        float az0 = 0.f, az1 = 0.f, al = 0.f;
        kz0 = 0.f; kz1 = 0.f;

        #pragma unroll 1
        for (int st = 0; st < 4; ++st) {
            const float cs = (st == 0) ? 0.f : ((st == 3) ? 1.f : 0.5f);
            const float as = cs * dt;
            const float ws = (st == 0 || st == 3) ? 1.f : 2.f;
            const float t  = t0 + as;

            // owner publishes this stage's input
            if (owner) {
                s.xs[wb + lane] = make_float2(fmaf(as, kz0, z0), fmaf(as, kz1, z1));
            }
            __syncthreads();   // also fences prior eval's sps/sgs reads

            // ---- layer-1 staging: softsig ONCE per (sample,k), swizzled cols ----
            {
                float2 x0v = s.xs[4 * sc + 0], x1v = s.xs[4 * sc + 1];
                float2 x2v = s.xs[4 * sc + 2], x3v = s.xs[4 * sc + 3];
                #pragma unroll
                for (int i = 0; i < 8; ++i) {
                    int k = kk * 8 + i;
                    float4 w  = s.w1[k ^ kk];      // k>>3 == kk
                    float  tb = fmaf(w.x, t, w.w);
                    float p0 = fmaf(w.y, x0v.x, fmaf(w.z, x0v.y, tb));
                    float p1 = fmaf(w.y, x1v.x, fmaf(w.z, x1v.y, tb));
                    float p2 = fmaf(w.y, x2v.x, fmaf(w.z, x2v.y, tb));
                    float p3 = fmaf(w.y, x3v.x, fmaf(w.z, x3v.y, tb));
                    float sp0, sg0, sp1, sg1, sp2, sg2, sp3, sg3;
                    softsig(p0, sp0, sg0); softsig(p1, sp1, sg1);
                    softsig(p2, sp2, sg2); softsig(p3, sp3, sg3);
                    int col = (4 * sc + 4 * kk) & 63;   // swizzled column
                    *(float4*)(s.sps + k * H + col) = make_float4(sp0, sp1, sp2, sp3);
                    *(float4*)(s.sgs + k * H + col) = make_float4(sg0, sg1, sg2, sg3);
                }
            }
            __syncthreads();

            // ---- k-loop: lane accumulates its (array, 8j, 8s) tile ----
            // acc[p][q]: p0=(4js,4js+1) p1=(4js+2,4js+3) p2=(32+4js,+1) p3=(32+4js+2,+3)
            unsigned long long acc[4][8];
            if (arr == 0) {
                #pragma unroll
                for (int p = 0; p < 4; ++p) {
                    int ci = ((p >> 1) ? 16 : 0) + 2 * js + (p & 1);
                    float4 cq = ((const float4*)s.c2)[ci];
                    unsigned long long ip = pack2(fmaf(cq.x, t, cq.y), fmaf(cq.z, t, cq.w));
                    #pragma unroll
                    for (int q = 0; q < 8; ++q) acc[p][q] = ip;
                }
            } else {
                #pragma unroll
                for (int p = 0; p < 4; ++p)
                    #pragma unroll
                    for (int q = 0; q < 8; ++q) acc[p][q] = 0ull;
            }

            const float* wbase = (arr ? s.mtr : s.w2r) + 4 * js;
            const float* abase = (arr ? s.sgs : s.sps);

            #pragma unroll 2
            for (int k = 0; k < H; ++k) {
                const float* row = wbase + k * H;
                ulonglong2 pA = *(const ulonglong2*)(row);        // j = 4js..4js+3
                ulonglong2 pB = *(const ulonglong2*)(row + 32);   // j = 32+4js..+3
                const int shift = 4 * (k >> 3);
                float4 a0 = *(const float4*)(abase + k * H + ((sbl + shift) & 63));
                float4 a1 = *(const float4*)(abase + k * H + ((sbl + 4 + shift) & 63));
                unsigned long long ds[8];
                ds[0] = pack2(a0.x, a0.x); ds[1] = pack2(a0.y, a0.y);
                ds[2] = pack2(a0.z, a0.z); ds[3] = pack2(a0.w, a0.w);
                ds[4] = pack2(a1.x, a1.x); ds[5] = pack2(a1.y, a1.y);
                ds[6] = pack2(a1.z, a1.z); ds[7] = pack2(a1.w, a1.w);
                #pragma unroll
                for (int q = 0; q < 8; ++q) {
                    acc[0][q] = fma2(pA.x, ds[q], acc[0][q]);
                    acc[1][q] = fma2(pA.y, ds[q], acc[1][q]);
                    acc[2][q] = fma2(pB.x, ds[q], acc[2][q]);
                    acc[3][q] = fma2(pB.y, ds[q], acc[3][q]);
                }
            }

            // ---- epilogue (role-split):
            //   arr0 lanes: sp-side -> zd0 (pA_), zd1 (pB_)
            //   arr1 lanes: sg-side -> dv  (pA_)  [acc2 shfl'd across]
            float pA_[8], pB_[8];
            #pragma unroll
            for (int q = 0; q < 8; ++q) { pA_[q] = 0.f; pB_[q] = 0.f; }

            #pragma unroll
            for (int p = 0; p < 4; ++p) {
                int li = ((p >> 1) ? 16 : 0) + 2 * js + (p & 1);
                float4 lq = ((const float4*)s.l3)[li];
                #pragma unroll
                for (int q = 0; q < 8; ++q) {
                    float2 av = unpack2(acc[p][q]);
                    float ox = __shfl_xor_sync(0xffffffffu, av.x, 16, 32);
                    float oy = __shfl_xor_sync(0xffffffffu, av.y, 16, 32);
                    // acc2 value for this lane's role:
                    float u0 = arr ? ox : av.x;
                    float u1 = arr ? oy : av.y;
                    float sp0, sg0, sp1, sg1;
                    softsig(u0, sp0, sg0);
                    softsig(u1, sp1, sg1);
                    if (arr == 0) {
                        pA_[q] = fmaf(lq.x, sp0, fmaf(lq.z, sp1, pA_[q]));  // zd0
                        pB_[q] = fmaf(lq.y, sp0, fmaf(lq.w, sp1, pB_[q]));  // zd1
                    } else {
                        pA_[q] = fmaf(sg0, av.x, fmaf(sg1, av.y, pA_[q]));  // dv
                    }
                }
            }

            // butterfly over the 8 j-groups (within each 8-lane octet)
            #pragma unroll
            for (int d = 1; d < 8; d <<= 1) {
                #pragma unroll
                for (int q = 0; q < 8; ++q) {
                    pA_[q] += __shfl_xor_sync(0xffffffffu, pA_[q], d, 32);
                    pB_[q] += __shfl_xor_sync(0xffffffffu, pB_[q], d, 32);
                }
            }

            // select own q = lane&7, then pull dv from partner lane^16
            float myA = 0.f, myB = 0.f;
            #pragma unroll
            for (int q = 0; q < 8; ++q)
                if (js == q) { myA = pA_[q]; myB = pB_[q]; }
            float partA = __shfl_xor_sync(0xffffffffu, myA, 16, 32);

            // owner: myA = zd0, myB = zd1, partA = dv (partner has same q)
            kz0 = fmaf(s.t3b[0], t, s.t3b[2]) + myA;
            kz1 = fmaf(s.t3b[1], t, s.t3b[3]) + myB;
            const float klv = -partA;

            az0 = fmaf(ws, kz0, az0);
            az1 = fmaf(ws, kz1, az1);
            al  = fmaf(ws, klv, al);
        }

        const float w6 = dt * (1.0f / 6.0f);
        z0 = fmaf(w6, az0, z0);
        z1 = fmaf(w6, az1, z1);
        lp = fmaf(w6, al,  lp);
    }

    if (owner && gs < B) {
        ((float2*)out)[gs] = make_float2(z0, z1);
        out[2 * B + gs] = lp;
    }
}

extern "C" void kernel_launch(void* const* d_in, const int* in_sizes, int n_in,
                              void* d_out, int out_size) {
    const float* z   = (const float*)d_in[0];
    const float* lp  = (const float*)d_in[1];
    const float* W1  = (const float*)d_in[2];
    const float* b1  = (const float*)d_in[3];
    const float* W2  = (const float*)d_in[4];
    const float* b2  = (const float*)d_in[5];
    const float* W3  = (const float*)d_in[6];
    const float* b3  = (const float*)d_in[7];
    const int B = in_sizes[0] / 2;

    const int smem = (int)sizeof(SWd);
    cudaFuncSetAttribute(ffjord_kernel, cudaFuncAttributeMaxDynamicSharedMemorySize, smem);

    const int blocks = (B + 63) / 64;   // 64 samples per CTA
    ffjord_kernel<<<blocks, THREADS, smem>>>(
        z, lp, W1, b1, W2, b2, W3, b3, (float*)d_out, B);
}